// round 11
// baseline (speedup 1.0000x reference)
#include <cuda_runtime.h>
#include <cuda_fp16.h>
#include <cstdint>
#include <cstddef>

// ===========================================================================
// StructureAttention, mma.sync fp16, fp32 accum.
// R11: CTA 64x256 (full N, LN fusion kept), 2 CTAs/SM (4 warps/SMSP) to
// cover per-iteration barrier stalls; QKV merged into one launch; fp16 Q/K/V.
// ===========================================================================

#define C_DIM 256
#define NB    4
#define MTOT  16777216

__device__ __half g_qkv[3 * MTOT];        // Q | K | V fp16
__device__ __half g_xh[MTOT];
__device__ __half g_mh[MTOT];
__device__ __half g_lh[MTOT];
__device__ __half g_hh[MTOT];
__device__ __half g_w[458752];
__device__ float g_small[32 * 1024 + 32 * 32];

// ---------------- helpers --------------------------------------------------
__device__ __forceinline__ uint32_t smem_u32(const void* p) {
    uint32_t a;
    asm("{ .reg .u64 t; cvta.to.shared.u64 t, %1; cvt.u32.u64 %0, t; }" : "=r"(a) : "l"(p));
    return a;
}
__device__ __forceinline__ void cp16(uint32_t dst, const void* src) {
    asm volatile("cp.async.cg.shared.global [%0], [%1], 16;"
                 :: "r"(dst), "l"(__cvta_generic_to_global(src)) : "memory");
}
#define CP_COMMIT() asm volatile("cp.async.commit_group;" ::: "memory")
#define CP_WAIT1()  asm volatile("cp.async.wait_group 1;"  ::: "memory")

__device__ __forceinline__ void ldsm4(uint32_t* r, uint32_t addr) {
    asm volatile("ldmatrix.sync.aligned.m8n8.x4.shared.b16 {%0,%1,%2,%3}, [%4];"
                 : "=r"(r[0]), "=r"(r[1]), "=r"(r[2]), "=r"(r[3]) : "r"(addr));
}
__device__ __forceinline__ void mma_fp16(float* c, const uint32_t* a, const uint32_t* b) {
    asm("mma.sync.aligned.m16n8k16.row.col.f32.f16.f16.f32 "
        "{%0,%1,%2,%3}, {%4,%5,%6,%7}, {%8,%9}, {%0,%1,%2,%3};"
        : "+f"(c[0]), "+f"(c[1]), "+f"(c[2]), "+f"(c[3])
        : "r"(a[0]), "r"(a[1]), "r"(a[2]), "r"(a[3]), "r"(b[0]), "r"(b[1]));
}
__device__ __forceinline__ float phi_f(float t) {
    return t > 0.f ? t + 1.f : __expf(t);
}

// ===========================================================================
// HMMA GEMM: out[M,256] = A[M,KDIM] * W[KDIM,256]; W transposed fp16
// (Wt[256,KDIM]); A fp16 (row len 256; KDIM=512 -> A1 = cols 256..511).
// CTA 64x256 (full N), BK=32, 3-stage cp.async, 8 warps = 2(m)x4(n),
// warp tile 32x64, fp32 accum, 2 CTAs/SM.
// OUTM: 1 = fp16 out (EPI: 0 none, 2 relu)
//       2 = LN + fp16 out ; 3 = LN + residual + fp32 out
//       4 = merged QKV: blockIdx.y selects weight/output, phi for y<2.
// ===========================================================================
#define A_PLANE   5120            // 64 rows * 80B
#define STAGE_B   25600           // A_PLANE + 256*80
#define GEMM_SMEM (3 * STAGE_B)   // 76800

template <int KDIM, int EPI, int OUTM>
__global__ __launch_bounds__(256, 2)
void gemm_mma(const __half* __restrict__ A0, const __half* __restrict__ A1,
              const __half* __restrict__ Bw,
              float* __restrict__ outF, __half* __restrict__ outH,
              const float* __restrict__ lng, const float* __restrict__ lnb,
              const float* __restrict__ res)
{
    extern __shared__ char dsm[];
    const uint32_t sb = smem_u32(dsm);

    const int tid    = threadIdx.x;
    const int lane   = tid & 31;
    const int wid    = tid >> 5;
    const int warp_m = wid >> 2;          // 0..1 (32 rows)
    const int warp_n = wid & 3;           // 0..3 (64 cols)
    const int m0     = blockIdx.x * 64;
    constexpr int NIT = KDIM / 32;

    const int wsel = (OUTM == 4) ? (int)blockIdx.y : 0;
    const __half* B = (OUTM == 4) ? Bw + (size_t)wsel * 65536 : Bw;
    __half* outH_ = (OUTM == 4) ? outH + (size_t)wsel * MTOT : outH;

    float acc[2][8][4];
#pragma unroll
    for (int mt = 0; mt < 2; ++mt)
#pragma unroll
        for (int nt = 0; nt < 8; ++nt)
#pragma unroll
            for (int q = 0; q < 4; ++q) acc[mt][nt][q] = 0.f;

    // 320 rows/stage: A rows 0..63, B rows 0..255. thread t -> rows t, t+256.
    auto load_stage = [&](int buf, int it) {
        const uint32_t st = sb + buf * STAGE_B;
        const int kc = it * 32;
        const __half* Ap; int kk = kc;
        if (KDIM == 512 && kc >= 256) { Ap = A1; kk = kc - 256; }
        else                          { Ap = A0; }
        {
            const int R = tid;
            const __half* srow;
            uint32_t drow;
            if (R < 64) { srow = Ap + (size_t)(m0 + R) * 256 + kk; drow = st + R * 80; }
            else        { srow = B + (size_t)(R - 64) * KDIM + kc; drow = st + A_PLANE + (R - 64) * 80; }
#pragma unroll
            for (int j = 0; j < 4; ++j) cp16(drow + j * 16, srow + j * 8);
        }
        {
            const int R = tid + 256;      // 256..511 -> B rows 192..447? no: rows 256-64=192..447 invalid
            if (R < 320) {
                const __half* srow = B + (size_t)(R - 64) * KDIM + kc;
                const uint32_t drow = st + A_PLANE + (R - 64) * 80;
#pragma unroll
                for (int j = 0; j < 4; ++j) cp16(drow + j * 16, srow + j * 8);
            }
        }
    };

    load_stage(0, 0); CP_COMMIT();
    load_stage(1, 1); CP_COMMIT();

    const int g  = lane >> 3;
    const int li = lane & 7;
    const int a_r  = li + (g & 1) * 8;
    const int a_kb = (g >> 1) * 16;
    const int b_r  = li + (g >> 1) * 8;
    const int b_kb = (g & 1) * 16;

    for (int it = 0; it < NIT; ++it) {
        CP_WAIT1();
        __syncthreads();
        if (it + 2 < NIT) load_stage((it + 2) % 3, it + 2);
        CP_COMMIT();

        const uint32_t st  = sb + (it % 3) * STAGE_B;
        const uint32_t stB = st + A_PLANE;

#pragma unroll
        for (int ks = 0; ks < 2; ++ks) {
            uint32_t aF[2][4];
#pragma unroll
            for (int mt = 0; mt < 2; ++mt) {
                const uint32_t ro = (uint32_t)((warp_m * 32 + mt * 16 + a_r) * 80 + ks * 32 + a_kb);
                ldsm4(aF[mt], st + ro);
            }
            uint32_t bF[8][2];
#pragma unroll
            for (int q = 0; q < 4; ++q) {
                const uint32_t ro = (uint32_t)((warp_n * 64 + q * 16 + b_r) * 80 + ks * 32 + b_kb);
                uint32_t t[4];
                ldsm4(t, stB + ro);
                bF[q * 2][0] = t[0]; bF[q * 2][1] = t[1];
                bF[q * 2 + 1][0] = t[2]; bF[q * 2 + 1][1] = t[3];
            }
#pragma unroll
            for (int mt = 0; mt < 2; ++mt)
#pragma unroll
                for (int nt = 0; nt < 8; ++nt)
                    mma_fp16(acc[mt][nt], aF[mt], bF[nt]);
        }
        __syncthreads();
    }

    // ------------------------- epilogue -----------------------------------
    const int orow = m0 + warp_m * 32 + (lane >> 2);
    const int ocol = warp_n * 64 + (lane & 3) * 2;

    if (OUTM == 1 || OUTM == 4) {
        const bool dophi = (OUTM == 4) && (wsel < 2);
#pragma unroll
        for (int mt = 0; mt < 2; ++mt) {
#pragma unroll
            for (int nt = 0; nt < 8; ++nt) {
                const int r = orow + mt * 16;
                const int c = ocol + nt * 8;
                float v0 = acc[mt][nt][0], v1 = acc[mt][nt][1];
                float v2 = acc[mt][nt][2], v3 = acc[mt][nt][3];
                if (EPI == 2) {
                    v0 = fmaxf(v0, 0.f); v1 = fmaxf(v1, 0.f);
                    v2 = fmaxf(v2, 0.f); v3 = fmaxf(v3, 0.f);
                }
                if (dophi) {
                    v0 = phi_f(v0); v1 = phi_f(v1);
                    v2 = phi_f(v2); v3 = phi_f(v3);
                }
                *(__half2*)&outH_[(size_t)r * 256 + c]       = __floats2half2_rn(v0, v1);
                *(__half2*)&outH_[(size_t)(r + 8) * 256 + c] = __floats2half2_rn(v2, v3);
            }
        }
    } else {
        // fused LayerNorm over the full 256-wide row.
        float* sbuf = (float*)dsm;             // [4 warp_n][64 rows][2]
        float rs[4], rq[4];
#pragma unroll
        for (int mt = 0; mt < 2; ++mt) {
#pragma unroll
            for (int h2 = 0; h2 < 2; ++h2) {
                float s = 0.f, q = 0.f;
#pragma unroll
                for (int nt = 0; nt < 8; ++nt) {
                    float u0 = acc[mt][nt][h2 * 2], u1 = acc[mt][nt][h2 * 2 + 1];
                    s += u0 + u1;
                    q += u0 * u0 + u1 * u1;
                }
#pragma unroll
                for (int o = 1; o < 4; o <<= 1) {
                    s += __shfl_xor_sync(0xffffffffu, s, o);
                    q += __shfl_xor_sync(0xffffffffu, q, o);
                }
                rs[mt * 2 + h2] = s;
                rq[mt * 2 + h2] = q;
            }
        }
        if ((lane & 3) == 0) {
            const int rg = lane >> 2;
#pragma unroll
            for (int mt = 0; mt < 2; ++mt)
#pragma unroll
                for (int h2 = 0; h2 < 2; ++h2) {
                    const int rl = warp_m * 32 + mt * 16 + h2 * 8 + rg;
                    sbuf[(warp_n * 64 + rl) * 2 + 0] = rs[mt * 2 + h2];
                    sbuf[(warp_n * 64 + rl) * 2 + 1] = rq[mt * 2 + h2];
                }
        }
        __syncthreads();
#pragma unroll
        for (int mt = 0; mt < 2; ++mt) {
#pragma unroll
            for (int h2 = 0; h2 < 2; ++h2) {
                const int rl = warp_m * 32 + mt * 16 + h2 * 8 + (lane >> 2);
                float s = 0.f, q = 0.f;
#pragma unroll
                for (int w = 0; w < 4; ++w) {
                    s += sbuf[(w * 64 + rl) * 2 + 0];
                    q += sbuf[(w * 64 + rl) * 2 + 1];
                }
                const float mu = s * (1.f / 256.f);
                const float var = q * (1.f / 256.f) - mu * mu;
                rs[mt * 2 + h2] = mu;
                rq[mt * 2 + h2] = rsqrtf(var + 1e-5f);
            }
        }
#pragma unroll
        for (int mt = 0; mt < 2; ++mt) {
#pragma unroll
            for (int nt = 0; nt < 8; ++nt) {
                const int c = ocol + nt * 8;
                const float2 gg = *(const float2*)&lng[c];
                const float2 bb = *(const float2*)&lnb[c];
#pragma unroll
                for (int h2 = 0; h2 < 2; ++h2) {
                    const int r = orow + mt * 16 + h2 * 8;
                    const float mu = rs[mt * 2 + h2];
                    const float rd = rq[mt * 2 + h2];
                    float v0 = (acc[mt][nt][h2 * 2]     - mu) * rd * gg.x + bb.x;
                    float v1 = (acc[mt][nt][h2 * 2 + 1] - mu) * rd * gg.y + bb.y;
                    if (OUTM == 2) {
                        *(__half2*)&outH_[(size_t)r * 256 + c] = __floats2half2_rn(v0, v1);
                    } else {
                        const float2 rr = *(const float2*)&res[(size_t)r * 256 + c];
                        float2 u; u.x = v0 + rr.x; u.y = v1 + rr.y;
                        *(float2*)&outF[(size_t)r * 256 + c] = u;
                    }
                }
            }
        }
    }
}

// ===========================================================================
// aux kernels
// ===========================================================================
__global__ void split_kernel(const float* __restrict__ in,
                             __half* __restrict__ out, int n4)
{
    int i = blockIdx.x * blockDim.x + threadIdx.x;
    if (i >= n4) return;
    float4 v = ((const float4*)in)[i];
    ((__half2*)out)[i * 2 + 0] = __floats2half2_rn(v.x, v.y);
    ((__half2*)out)[i * 2 + 1] = __floats2half2_rn(v.z, v.w);
}

// all weights, transposed to [N, K] fp16. wq@0 wk@65536 wv@131072 wm@196608
// w2@262144 (K=256); w1@327680 (K=512)
__global__ void wprep_all(const float* __restrict__ Wq, const float* __restrict__ Wk,
                          const float* __restrict__ Wv, const float* __restrict__ Wm,
                          const float* __restrict__ W2, const float* __restrict__ W1,
                          __half* __restrict__ dst)
{
    int idx = blockIdx.x * blockDim.x + threadIdx.x;
    const float* W; int K; int within; __half* o;
    if (idx < 327680) {
        int w = idx >> 16; within = idx & 65535; K = 256;
        const float* srcs[5] = {Wq, Wk, Wv, Wm, W2};
        W = srcs[w];
        o = dst + w * 65536;
    } else if (idx < 458752) {
        within = idx - 327680; K = 512; W = W1;
        o = dst + 327680;
    } else return;
    int nn = within / K, kk = within % K;
    o[(size_t)nn * K + kk] = __float2half_rn(W[(size_t)kk * 256 + nn]);
}

__global__ void zero_kernel(float* p, int n)
{
    int i = blockIdx.x * blockDim.x + threadIdx.x;
    if (i < n) p[i] = 0.f;
}

__global__ __launch_bounds__(1024) void kv_reduce_kernel(
    const __half* __restrict__ Kp, const __half* __restrict__ Vp,
    float* __restrict__ KV, float* __restrict__ Ksum, int L)
{
    const int nh = blockIdx.x;
    const int n  = nh >> 3;
    const int h  = nh & 7;
    const int rows = L / gridDim.y;        // 256
    const int l0 = blockIdx.y * rows;
    const int tid = threadIdx.x;
    const int d = tid >> 5;
    const int e = tid & 31;

    __shared__ float sk[64][32];
    __shared__ float sv[64][32];

    const size_t base = (size_t)n * L * 256 + h * 32;

    float acc = 0.f, ks = 0.f;
    for (int l = l0; l < l0 + rows; l += 64) {
        __syncthreads();
#pragma unroll
        for (int c = 0; c < 2; ++c) {
            const int idx2 = tid + c * 1024;       // 0..2047 (half2 units)
            const int row = idx2 >> 5;
            const int cp  = idx2 & 31;
            size_t off = base + (size_t)(l + row) * 256;
            if (cp < 16) {
                __half2 v = *(const __half2*)&Kp[off + cp * 2];
                float2 f = __half22float2(v);
                sk[row][cp * 2] = f.x; sk[row][cp * 2 + 1] = f.y;
            } else {
                __half2 v = *(const __half2*)&Vp[off + (cp - 16) * 2];
                float2 f = __half22float2(v);
                sv[row][(cp - 16) * 2] = f.x; sv[row][(cp - 16) * 2 + 1] = f.y;
            }
        }
        __syncthreads();
#pragma unroll
        for (int r = 0; r < 64; ++r) acc += sk[r][d] * sv[r][e];
        if (e == 0) {
#pragma unroll
            for (int r = 0; r < 64; ++r) ks += sk[r][d];
        }
    }
    atomicAdd(&KV[(size_t)nh * 1024 + d * 32 + e], acc);
    if (e == 0) atomicAdd(&Ksum[nh * 32 + d], ks);
}

__global__ __launch_bounds__(256) void msg_kernel(
    const __half* __restrict__ Q, const float* __restrict__ KV,
    const float* __restrict__ Ksum,
    __half* __restrict__ MH, int L)
{
    const int row = blockIdx.x;
    const int n = row / L;
    const int tid = threadIdx.x;
    const int h = tid >> 5;
    const int e = tid & 31;

    __shared__ float qs[256];
    qs[tid] = __half2float(Q[(size_t)row * 256 + tid]);
    __syncthreads();

    float p = qs[h * 32 + e] * Ksum[(n * 8 + h) * 32 + e];
#pragma unroll
    for (int o = 16; o; o >>= 1) p += __shfl_xor_sync(0xffffffffu, p, o);
    const float z = 1.f / (p + 1e-6f);

    const float* kv = KV + (size_t)(n * 8 + h) * 1024;
    float acc = 0.f;
#pragma unroll
    for (int dd = 0; dd < 32; ++dd) acc += qs[h * 32 + dd] * kv[dd * 32 + e];

    MH[(size_t)row * 256 + tid] = __float2half_rn(acc * z);
}

// ===========================================================================
// launch
// ===========================================================================
extern "C" void kernel_launch(void* const* d_in, const int* in_sizes, int n_in,
                              void* d_out, int out_size)
{
    const float* x  = (const float*)d_in[0];
    const float* Wq = (const float*)d_in[1];
    const float* Wk = (const float*)d_in[2];
    const float* Wv = (const float*)d_in[3];
    const float* Wm = (const float*)d_in[4];
    const float* W1 = (const float*)d_in[5];
    const float* W2 = (const float*)d_in[6];
    const float* g1 = (const float*)d_in[7];
    const float* b1 = (const float*)d_in[8];
    const float* g2 = (const float*)d_in[9];
    const float* b2 = (const float*)d_in[10];

    const int M = in_sizes[0] / C_DIM;   // 65536
    const int L = M / NB;                // 16384

    float* sm;
    __half *qkv, *xh, *mh, *lh, *hh, *gw;
    cudaGetSymbolAddress((void**)&qkv, g_qkv);
    cudaGetSymbolAddress((void**)&xh, g_xh);
    cudaGetSymbolAddress((void**)&mh, g_mh);
    cudaGetSymbolAddress((void**)&lh, g_lh);
    cudaGetSymbolAddress((void**)&hh, g_hh);
    cudaGetSymbolAddress((void**)&gw, g_w);
    cudaGetSymbolAddress((void**)&sm, g_small);
    float* KV   = sm;
    float* Ksum = sm + 32 * 1024;

    __half *wm = gw + 196608;
    __half *w2 = gw + 262144;
    __half *w1 = gw + 327680;
    __half *Qh = qkv;
    __half *Kh = qkv + MTOT;
    __half *Vh = qkv + 2 * MTOT;

    cudaFuncSetAttribute(gemm_mma<256, 0, 4>, cudaFuncAttributeMaxDynamicSharedMemorySize, GEMM_SMEM);
    cudaFuncSetAttribute(gemm_mma<256, 0, 2>, cudaFuncAttributeMaxDynamicSharedMemorySize, GEMM_SMEM);
    cudaFuncSetAttribute(gemm_mma<512, 2, 1>, cudaFuncAttributeMaxDynamicSharedMemorySize, GEMM_SMEM);
    cudaFuncSetAttribute(gemm_mma<256, 0, 3>, cudaFuncAttributeMaxDynamicSharedMemorySize, GEMM_SMEM);

    wprep_all<<<(458752 + 255) / 256, 256>>>(Wq, Wk, Wv, Wm, W2, W1, gw);
    split_kernel<<<(M * 64 + 255) / 256, 256>>>(x, xh, M * 64);

    const int GB = M / 64;   // 1024 m-blocks

    // merged q,k,v (phi fused for q,k) -> fp16 planes
    gemm_mma<256, 0, 4><<<dim3(GB, 3), 256, GEMM_SMEM>>>(
        xh, nullptr, gw, nullptr, qkv, nullptr, nullptr, nullptr);

    zero_kernel<<<(33792 + 255) / 256, 256>>>(sm, 33792);
    kv_reduce_kernel<<<dim3(32, 64), 1024>>>(Kh, Vh, KV, Ksum, L);

    msg_kernel<<<M, 256>>>(Qh, KV, Ksum, mh, L);

    // msg @ Wm with fused LN1 -> lh (fp16)
    gemm_mma<256, 0, 2><<<GB, 256, GEMM_SMEM>>>(mh, nullptr, wm, nullptr, lh, g1, b1, nullptr);

    // relu([x, ln1] @ W1) -> hh (fp16)
    gemm_mma<512, 2, 1><<<GB, 256, GEMM_SMEM>>>(xh, lh, w1, nullptr, hh, nullptr, nullptr, nullptr);

    // h @ W2 with fused LN2 + residual -> d_out (fp32)
    gemm_mma<256, 0, 3><<<GB, 256, GEMM_SMEM>>>(hh, nullptr, w2, (float*)d_out, nullptr, g2, b2, x);
}

// round 13
// speedup vs baseline: 1.1866x; 1.1866x over previous
#include <cuda_runtime.h>
#include <cuda_fp16.h>
#include <cstdint>
#include <cstddef>

// ===========================================================================
// StructureAttention, mma.sync fp16, fp32 accum.
// R13 (= R12 re-bench after infra flake): resident-B persistent GEMM for all
// K=256 units (B=128KB in smem, loaded once per CTA; A streamed 3x10KB).
// R10 geometry (128x256, warp 64x64). W1 (K=512) streaming. fp16 QKV,
// merged QKV launch.
// ===========================================================================

#define C_DIM 256
#define NB    4
#define MTOT  16777216

__device__ __half g_qkv[3 * MTOT];        // Q | K | V fp16
__device__ __half g_xh[MTOT];
__device__ __half g_mh[MTOT];
__device__ __half g_lh[MTOT];
__device__ __half g_hh[MTOT];
__device__ __half g_w[458752];
__device__ float g_small[32 * 1024 + 32 * 32];

// ---------------- helpers --------------------------------------------------
__device__ __forceinline__ uint32_t smem_u32(const void* p) {
    uint32_t a;
    asm("{ .reg .u64 t; cvta.to.shared.u64 t, %1; cvt.u32.u64 %0, t; }" : "=r"(a) : "l"(p));
    return a;
}
__device__ __forceinline__ void cp16(uint32_t dst, const void* src) {
    asm volatile("cp.async.cg.shared.global [%0], [%1], 16;"
                 :: "r"(dst), "l"(__cvta_generic_to_global(src)) : "memory");
}
#define CP_COMMIT() asm volatile("cp.async.commit_group;" ::: "memory")
#define CP_WAIT1()  asm volatile("cp.async.wait_group 1;"  ::: "memory")
#define CP_WAIT0()  asm volatile("cp.async.wait_group 0;"  ::: "memory")

__device__ __forceinline__ void ldsm4(uint32_t* r, uint32_t addr) {
    asm volatile("ldmatrix.sync.aligned.m8n8.x4.shared.b16 {%0,%1,%2,%3}, [%4];"
                 : "=r"(r[0]), "=r"(r[1]), "=r"(r[2]), "=r"(r[3]) : "r"(addr));
}
__device__ __forceinline__ void mma_fp16(float* c, const uint32_t* a, const uint32_t* b) {
    asm("mma.sync.aligned.m16n8k16.row.col.f32.f16.f16.f32 "
        "{%0,%1,%2,%3}, {%4,%5,%6,%7}, {%8,%9}, {%0,%1,%2,%3};"
        : "+f"(c[0]), "+f"(c[1]), "+f"(c[2]), "+f"(c[3])
        : "r"(a[0]), "r"(a[1]), "r"(a[2]), "r"(a[3]), "r"(b[0]), "r"(b[1]));
}
__device__ __forceinline__ float phi_f(float t) {
    return t > 0.f ? t + 1.f : __expf(t);
}

// ===========================================================================
// Resident-B persistent GEMM (K=256): out[M,256] = A[M,256] * W[256,256].
// Wt[256,256] fp16 resident in smem (528B row stride -> ldmatrix
// conflict-free). A streamed: 3 x 10KB stages. CTA tile 128x256,
// 8 warps = 2(m)x4(n), warp tile 64x64, grid-strided m-tiles.
// OUTM: 2 = LN+fp16 ; 3 = LN+residual+fp32 ; 4 = QKV (blockIdx.y, phi y<2).
// ===========================================================================
#define A_PLANE   10240           // 128 rows * 80B
#define B_ROW     528
#define B_OFF     (3 * A_PLANE)   // 30720
#define RES_SMEM  (B_OFF + 256 * B_ROW)   // 165888

template <int OUTM>
__global__ __launch_bounds__(256, 1)
void gemm_res(const __half* __restrict__ A0, const __half* __restrict__ Bw,
              float* __restrict__ outF, __half* __restrict__ outH,
              const float* __restrict__ lng, const float* __restrict__ lnb,
              const float* __restrict__ res, int Mrows)
{
    extern __shared__ char dsm[];
    const uint32_t sb = smem_u32(dsm);
    const int tid    = threadIdx.x;
    const int lane   = tid & 31;
    const int wid    = tid >> 5;
    const int warp_m = wid >> 2;          // 0..1
    const int warp_n = wid & 3;           // 0..3

    const int wsel = (OUTM == 4) ? (int)blockIdx.y : 0;
    const __half* B = (OUTM == 4) ? Bw + (size_t)wsel * 65536 : Bw;
    __half* outH_ = (OUTM == 4) ? outH + (size_t)wsel * MTOT : outH;

    // ---- load whole B resident: 256 rows x 512B, one row per thread ------
    {
        const __half* srow = B + (size_t)tid * 256;
        const uint32_t drow = sb + B_OFF + tid * B_ROW;
#pragma unroll
        for (int j = 0; j < 32; ++j) cp16(drow + j * 16, srow + j * 8);
    }
    CP_COMMIT();
    CP_WAIT0();
    __syncthreads();

    const int g  = lane >> 3;
    const int li = lane & 7;
    const int a_r  = li + (g & 1) * 8;
    const int a_kb = (g >> 1) * 16;
    const int b_r  = li + (g >> 1) * 8;
    const int b_kb = (g & 1) * 16;

    const int a_row = tid >> 1;           // 0..127
    const int a_j0  = (tid & 1) * 2;      // chunk base (0 or 2)

    const uint32_t stB = sb + B_OFF;

    for (int m0 = blockIdx.x * 128; m0 < Mrows; m0 += gridDim.x * 128) {
        float acc[4][8][4];
#pragma unroll
        for (int mt = 0; mt < 4; ++mt)
#pragma unroll
            for (int nt = 0; nt < 8; ++nt)
#pragma unroll
                for (int q = 0; q < 4; ++q) acc[mt][nt][q] = 0.f;

        auto load_a = [&](int buf, int it) {
            const __half* srow = A0 + (size_t)(m0 + a_row) * 256 + it * 32 + a_j0 * 8;
            const uint32_t drow = sb + buf * A_PLANE + a_row * 80 + a_j0 * 16;
            cp16(drow, srow);
            cp16(drow + 16, srow + 8);
        };

        load_a(0, 0); CP_COMMIT();
        load_a(1, 1); CP_COMMIT();

        for (int it = 0; it < 8; ++it) {
            CP_WAIT1();
            __syncthreads();
            if (it + 2 < 8) load_a((it + 2) % 3, it + 2);
            CP_COMMIT();

            const uint32_t st = sb + (it % 3) * A_PLANE;
#pragma unroll
            for (int ks = 0; ks < 2; ++ks) {
                uint32_t aF[4][4];
#pragma unroll
                for (int mt = 0; mt < 4; ++mt) {
                    const uint32_t ro = (uint32_t)((warp_m * 64 + mt * 16 + a_r) * 80 + ks * 32 + a_kb);
                    ldsm4(aF[mt], st + ro);
                }
                uint32_t bF[8][2];
#pragma unroll
                for (int q = 0; q < 4; ++q) {
                    const uint32_t ro = (uint32_t)((warp_n * 64 + q * 16 + b_r) * B_ROW + it * 64 + ks * 32 + b_kb);
                    uint32_t t[4];
                    ldsm4(t, stB + ro);
                    bF[q * 2][0] = t[0]; bF[q * 2][1] = t[1];
                    bF[q * 2 + 1][0] = t[2]; bF[q * 2 + 1][1] = t[3];
                }
#pragma unroll
                for (int mt = 0; mt < 4; ++mt)
#pragma unroll
                    for (int nt = 0; nt < 8; ++nt)
                        mma_fp16(acc[mt][nt], aF[mt], bF[nt]);
            }
            __syncthreads();
        }

        // ------------------------- epilogue --------------------------------
        const int orow = m0 + warp_m * 64 + (lane >> 2);
        const int ocol = warp_n * 64 + (lane & 3) * 2;

        if (OUTM == 4) {
            const bool dophi = (wsel < 2);
#pragma unroll
            for (int mt = 0; mt < 4; ++mt) {
#pragma unroll
                for (int nt = 0; nt < 8; ++nt) {
                    const int r = orow + mt * 16;
                    const int c = ocol + nt * 8;
                    float v0 = acc[mt][nt][0], v1 = acc[mt][nt][1];
                    float v2 = acc[mt][nt][2], v3 = acc[mt][nt][3];
                    if (dophi) {
                        v0 = phi_f(v0); v1 = phi_f(v1);
                        v2 = phi_f(v2); v3 = phi_f(v3);
                    }
                    *(__half2*)&outH_[(size_t)r * 256 + c]       = __floats2half2_rn(v0, v1);
                    *(__half2*)&outH_[(size_t)(r + 8) * 256 + c] = __floats2half2_rn(v2, v3);
                }
            }
        } else {
            // fused LayerNorm over full 256-wide rows. sbuf overlaps A buf0
            // (safe: buf0's last consumer was it=6, followed by syncthreads;
            // trailing syncthreads below protects the next tile).
            float* sbuf = (float*)dsm;         // [4][128][2]
            float rs[8], rq[8];
#pragma unroll
            for (int mt = 0; mt < 4; ++mt) {
#pragma unroll
                for (int h2 = 0; h2 < 2; ++h2) {
                    float s = 0.f, q = 0.f;
#pragma unroll
                    for (int nt = 0; nt < 8; ++nt) {
                        float u0 = acc[mt][nt][h2 * 2], u1 = acc[mt][nt][h2 * 2 + 1];
                        s += u0 + u1;
                        q += u0 * u0 + u1 * u1;
                    }
#pragma unroll
                    for (int o = 1; o < 4; o <<= 1) {
                        s += __shfl_xor_sync(0xffffffffu, s, o);
                        q += __shfl_xor_sync(0xffffffffu, q, o);
                    }
                    rs[mt * 2 + h2] = s;
                    rq[mt * 2 + h2] = q;
                }
            }
            if ((lane & 3) == 0) {
                const int rg = lane >> 2;
#pragma unroll
                for (int mt = 0; mt < 4; ++mt)
#pragma unroll
                    for (int h2 = 0; h2 < 2; ++h2) {
                        const int rl = warp_m * 64 + mt * 16 + h2 * 8 + rg;
                        sbuf[(warp_n * 128 + rl) * 2 + 0] = rs[mt * 2 + h2];
                        sbuf[(warp_n * 128 + rl) * 2 + 1] = rq[mt * 2 + h2];
                    }
            }
            __syncthreads();
#pragma unroll
            for (int mt = 0; mt < 4; ++mt) {
#pragma unroll
                for (int h2 = 0; h2 < 2; ++h2) {
                    const int rl = warp_m * 64 + mt * 16 + h2 * 8 + (lane >> 2);
                    float s = 0.f, q = 0.f;
#pragma unroll
                    for (int w = 0; w < 4; ++w) {
                        s += sbuf[(w * 128 + rl) * 2 + 0];
                        q += sbuf[(w * 128 + rl) * 2 + 1];
                    }
                    const float mu = s * (1.f / 256.f);
                    const float var = q * (1.f / 256.f) - mu * mu;
                    rs[mt * 2 + h2] = mu;
                    rq[mt * 2 + h2] = rsqrtf(var + 1e-5f);
                }
            }
#pragma unroll
            for (int mt = 0; mt < 4; ++mt) {
#pragma unroll
                for (int nt = 0; nt < 8; ++nt) {
                    const int c = ocol + nt * 8;
                    const float2 gg = *(const float2*)&lng[c];
                    const float2 bb = *(const float2*)&lnb[c];
#pragma unroll
                    for (int h2 = 0; h2 < 2; ++h2) {
                        const int r = orow + mt * 16 + h2 * 8;
                        const float mu = rs[mt * 2 + h2];
                        const float rd = rq[mt * 2 + h2];
                        float v0 = (acc[mt][nt][h2 * 2]     - mu) * rd * gg.x + bb.x;
                        float v1 = (acc[mt][nt][h2 * 2 + 1] - mu) * rd * gg.y + bb.y;
                        if (OUTM == 2) {
                            *(__half2*)&outH_[(size_t)r * 256 + c] = __floats2half2_rn(v0, v1);
                        } else {
                            const float2 rr = *(const float2*)&res[(size_t)r * 256 + c];
                            float2 u; u.x = v0 + rr.x; u.y = v1 + rr.y;
                            *(float2*)&outF[(size_t)r * 256 + c] = u;
                        }
                    }
                }
            }
        }
        __syncthreads();   // protect smem (A bufs / LN sbuf) before next tile
    }
}

// ===========================================================================
// Streaming GEMM for K=512 (W1): relu([x, ln1] @ W1) -> fp16. R10 design.
// ===========================================================================
#define SA_PLANE   10240
#define STAGE_B    30720
#define STREAM_SMEM (3 * STAGE_B)

__global__ __launch_bounds__(256, 1)
void gemm_stream512(const __half* __restrict__ A0, const __half* __restrict__ A1,
                    const __half* __restrict__ B, __half* __restrict__ outH)
{
    extern __shared__ char dsm[];
    const uint32_t sb = smem_u32(dsm);

    const int tid    = threadIdx.x;
    const int lane   = tid & 31;
    const int wid    = tid >> 5;
    const int warp_m = wid >> 2;
    const int warp_n = wid & 3;
    const int m0     = blockIdx.x * 128;
    constexpr int NIT = 16;

    float acc[4][8][4];
#pragma unroll
    for (int mt = 0; mt < 4; ++mt)
#pragma unroll
        for (int nt = 0; nt < 8; ++nt)
#pragma unroll
            for (int q = 0; q < 4; ++q) acc[mt][nt][q] = 0.f;

    auto load_stage = [&](int buf, int it) {
        const uint32_t st = sb + buf * STAGE_B;
        const int kc = it * 32;
        const __half* Ap; int kk = kc;
        if (kc >= 256) { Ap = A1; kk = kc - 256; }
        else           { Ap = A0; }
#pragma unroll
        for (int rr = 0; rr < 2; ++rr) {
            const int R = tid + rr * 256;
            if (R < 128) {
                const __half* srow = Ap + (size_t)(m0 + R) * 256 + kk;
                const uint32_t drow = st + R * 80;
#pragma unroll
                for (int j = 0; j < 4; ++j) cp16(drow + j * 16, srow + j * 8);
            } else if (R < 384) {
                const __half* srow = B + (size_t)(R - 128) * 512 + kc;
                const uint32_t drow = st + SA_PLANE + (R - 128) * 80;
#pragma unroll
                for (int j = 0; j < 4; ++j) cp16(drow + j * 16, srow + j * 8);
            }
        }
    };

    load_stage(0, 0); CP_COMMIT();
    load_stage(1, 1); CP_COMMIT();

    const int g  = lane >> 3;
    const int li = lane & 7;
    const int a_r  = li + (g & 1) * 8;
    const int a_kb = (g >> 1) * 16;
    const int b_r  = li + (g >> 1) * 8;
    const int b_kb = (g & 1) * 16;

    for (int it = 0; it < NIT; ++it) {
        CP_WAIT1();
        __syncthreads();
        if (it + 2 < NIT) load_stage((it + 2) % 3, it + 2);
        CP_COMMIT();

        const uint32_t st  = sb + (it % 3) * STAGE_B;
        const uint32_t stB = st + SA_PLANE;

#pragma unroll
        for (int ks = 0; ks < 2; ++ks) {
            uint32_t aF[4][4];
#pragma unroll
            for (int mt = 0; mt < 4; ++mt) {
                const uint32_t ro = (uint32_t)((warp_m * 64 + mt * 16 + a_r) * 80 + ks * 32 + a_kb);
                ldsm4(aF[mt], st + ro);
            }
            uint32_t bF[8][2];
#pragma unroll
            for (int q = 0; q < 4; ++q) {
                const uint32_t ro = (uint32_t)((warp_n * 64 + q * 16 + b_r) * 80 + ks * 32 + b_kb);
                uint32_t t[4];
                ldsm4(t, stB + ro);
                bF[q * 2][0] = t[0]; bF[q * 2][1] = t[1];
                bF[q * 2 + 1][0] = t[2]; bF[q * 2 + 1][1] = t[3];
            }
#pragma unroll
            for (int mt = 0; mt < 4; ++mt)
#pragma unroll
                for (int nt = 0; nt < 8; ++nt)
                    mma_fp16(acc[mt][nt], aF[mt], bF[nt]);
        }
        __syncthreads();
    }

    const int orow = m0 + warp_m * 64 + (lane >> 2);
    const int ocol = warp_n * 64 + (lane & 3) * 2;
#pragma unroll
    for (int mt = 0; mt < 4; ++mt) {
#pragma unroll
        for (int nt = 0; nt < 8; ++nt) {
            const int r = orow + mt * 16;
            const int c = ocol + nt * 8;
            float v0 = fmaxf(acc[mt][nt][0], 0.f);
            float v1 = fmaxf(acc[mt][nt][1], 0.f);
            float v2 = fmaxf(acc[mt][nt][2], 0.f);
            float v3 = fmaxf(acc[mt][nt][3], 0.f);
            *(__half2*)&outH[(size_t)r * 256 + c]       = __floats2half2_rn(v0, v1);
            *(__half2*)&outH[(size_t)(r + 8) * 256 + c] = __floats2half2_rn(v2, v3);
        }
    }
}

// ===========================================================================
// aux kernels
// ===========================================================================
__global__ void split_kernel(const float* __restrict__ in,
                             __half* __restrict__ out, int n4)
{
    int i = blockIdx.x * blockDim.x + threadIdx.x;
    if (i >= n4) return;
    float4 v = ((const float4*)in)[i];
    ((__half2*)out)[i * 2 + 0] = __floats2half2_rn(v.x, v.y);
    ((__half2*)out)[i * 2 + 1] = __floats2half2_rn(v.z, v.w);
}

__global__ void wprep_all(const float* __restrict__ Wq, const float* __restrict__ Wk,
                          const float* __restrict__ Wv, const float* __restrict__ Wm,
                          const float* __restrict__ W2, const float* __restrict__ W1,
                          __half* __restrict__ dst)
{
    int idx = blockIdx.x * blockDim.x + threadIdx.x;
    const float* W; int K; int within; __half* o;
    if (idx < 327680) {
        int w = idx >> 16; within = idx & 65535; K = 256;
        const float* srcs[5] = {Wq, Wk, Wv, Wm, W2};
        W = srcs[w];
        o = dst + w * 65536;
    } else if (idx < 458752) {
        within = idx - 327680; K = 512; W = W1;
        o = dst + 327680;
    } else return;
    int nn = within / K, kk = within % K;
    o[(size_t)nn * K + kk] = __float2half_rn(W[(size_t)kk * 256 + nn]);
}

__global__ void zero_kernel(float* p, int n)
{
    int i = blockIdx.x * blockDim.x + threadIdx.x;
    if (i < n) p[i] = 0.f;
}

__global__ __launch_bounds__(1024) void kv_reduce_kernel(
    const __half* __restrict__ Kp, const __half* __restrict__ Vp,
    float* __restrict__ KV, float* __restrict__ Ksum, int L)
{
    const int nh = blockIdx.x;
    const int n  = nh >> 3;
    const int h  = nh & 7;
    const int rows = L / gridDim.y;        // 256
    const int l0 = blockIdx.y * rows;
    const int tid = threadIdx.x;
    const int d = tid >> 5;
    const int e = tid & 31;

    __shared__ float sk[64][32];
    __shared__ float sv[64][32];

    const size_t base = (size_t)n * L * 256 + h * 32;

    float acc = 0.f, ks = 0.f;
    for (int l = l0; l < l0 + rows; l += 64) {
        __syncthreads();
#pragma unroll
        for (int c = 0; c < 2; ++c) {
            const int idx2 = tid + c * 1024;
            const int row = idx2 >> 5;
            const int cp  = idx2 & 31;
            size_t off = base + (size_t)(l + row) * 256;
            if (cp < 16) {
                __half2 v = *(const __half2*)&Kp[off + cp * 2];
                float2 f = __half22float2(v);
                sk[row][cp * 2] = f.x; sk[row][cp * 2 + 1] = f.y;
            } else {
                __half2 v = *(const __half2*)&Vp[off + (cp - 16) * 2];
                float2 f = __half22float2(v);
                sv[row][(cp - 16) * 2] = f.x; sv[row][(cp - 16) * 2 + 1] = f.y;
            }
        }
        __syncthreads();
#pragma unroll
        for (int r = 0; r < 64; ++r) acc += sk[r][d] * sv[r][e];
        if (e == 0) {
#pragma unroll
            for (int r = 0; r < 64; ++r) ks += sk[r][d];
        }
    }
    atomicAdd(&KV[(size_t)nh * 1024 + d * 32 + e], acc);
    if (e == 0) atomicAdd(&Ksum[nh * 32 + d], ks);
}

__global__ __launch_bounds__(256) void msg_kernel(
    const __half* __restrict__ Q, const float* __restrict__ KV,
    const float* __restrict__ Ksum,
    __half* __restrict__ MH, int L)
{
    const int row = blockIdx.x;
    const int n = row / L;
    const int tid = threadIdx.x;
    const int h = tid >> 5;
    const int e = tid & 31;

    __shared__ float qs[256];
    qs[tid] = __half2float(Q[(size_t)row * 256 + tid]);
    __syncthreads();

    float p = qs[h * 32 + e] * Ksum[(n * 8 + h) * 32 + e];
#pragma unroll
    for (int o = 16; o; o >>= 1) p += __shfl_xor_sync(0xffffffffu, p, o);
    const float z = 1.f / (p + 1e-6f);

    const float* kv = KV + (size_t)(n * 8 + h) * 1024;
    float acc = 0.f;
#pragma unroll
    for (int dd = 0; dd < 32; ++dd) acc += qs[h * 32 + dd] * kv[dd * 32 + e];

    MH[(size_t)row * 256 + tid] = __float2half_rn(acc * z);
}

// ===========================================================================
// launch
// ===========================================================================
extern "C" void kernel_launch(void* const* d_in, const int* in_sizes, int n_in,
                              void* d_out, int out_size)
{
    const float* x  = (const float*)d_in[0];
    const float* Wq = (const float*)d_in[1];
    const float* Wk = (const float*)d_in[2];
    const float* Wv = (const float*)d_in[3];
    const float* Wm = (const float*)d_in[4];
    const float* W1 = (const float*)d_in[5];
    const float* W2 = (const float*)d_in[6];
    const float* g1 = (const float*)d_in[7];
    const float* b1 = (const float*)d_in[8];
    const float* g2 = (const float*)d_in[9];
    const float* b2 = (const float*)d_in[10];

    const int M = in_sizes[0] / C_DIM;   // 65536
    const int L = M / NB;                // 16384

    float* sm;
    __half *qkv, *xh, *mh, *lh, *hh, *gw;
    cudaGetSymbolAddress((void**)&qkv, g_qkv);
    cudaGetSymbolAddress((void**)&xh, g_xh);
    cudaGetSymbolAddress((void**)&mh, g_mh);
    cudaGetSymbolAddress((void**)&lh, g_lh);
    cudaGetSymbolAddress((void**)&hh, g_hh);
    cudaGetSymbolAddress((void**)&gw, g_w);
    cudaGetSymbolAddress((void**)&sm, g_small);
    float* KV   = sm;
    float* Ksum = sm + 32 * 1024;

    __half *wm = gw + 196608;
    __half *w2 = gw + 262144;
    __half *w1 = gw + 327680;
    __half *Qh = qkv;
    __half *Kh = qkv + MTOT;
    __half *Vh = qkv + 2 * MTOT;

    cudaFuncSetAttribute(gemm_res<4>, cudaFuncAttributeMaxDynamicSharedMemorySize, RES_SMEM);
    cudaFuncSetAttribute(gemm_res<2>, cudaFuncAttributeMaxDynamicSharedMemorySize, RES_SMEM);
    cudaFuncSetAttribute(gemm_res<3>, cudaFuncAttributeMaxDynamicSharedMemorySize, RES_SMEM);
    cudaFuncSetAttribute(gemm_stream512, cudaFuncAttributeMaxDynamicSharedMemorySize, STREAM_SMEM);

    wprep_all<<<(458752 + 255) / 256, 256>>>(Wq, Wk, Wv, Wm, W2, W1, gw);
    split_kernel<<<(M * 64 + 255) / 256, 256>>>(x, xh, M * 64);

    // merged q,k,v (phi fused for q,k), resident-B persistent
    gemm_res<4><<<dim3(148, 3), 256, RES_SMEM>>>(
        xh, gw, nullptr, qkv, nullptr, nullptr, nullptr, M);

    zero_kernel<<<(33792 + 255) / 256, 256>>>(sm, 33792);
    kv_reduce_kernel<<<dim3(32, 64), 1024>>>(Kh, Vh, KV, Ksum, L);

    msg_kernel<<<M, 256>>>(Qh, KV, Ksum, mh, L);

    // msg @ Wm with fused LN1 -> lh (fp16)
    gemm_res<2><<<148, 256, RES_SMEM>>>(mh, wm, nullptr, lh, g1, b1, nullptr, M);

    // relu([x, ln1] @ W1) -> hh (fp16), streaming K=512
    gemm_stream512<<<M / 128, 256, STREAM_SMEM>>>(xh, lh, w1, hh);

    // h @ W2 with fused LN2 + residual -> d_out (fp32)
    gemm_res<3><<<148, 256, RES_SMEM>>>(hh, w2, (float*)d_out, nullptr, g2, b2, x, M);
}